// round 1
// baseline (speedup 1.0000x reference)
#include <cuda_runtime.h>
#include <cuda_bf16.h>
#include <math.h>

#define NN 100000
#define EE 200000
#define GG 2000
#define DD 300
#define D2 600
#define LL 5
#define FT 512
#define MAXDEG 4
#define BN_EPS 1e-5f

// ---------------- scratch (device globals; no allocation) ----------------
__device__ float d_h[NN * DD];
__device__ float d_agg[NN * DD];      // also reused as "fused" before layer 0
__device__ float d_hidden[NN * D2];
__device__ float d_hin[NN * DD];
__device__ int   d_counts[NN];
__device__ int   d_deg[NN];
__device__ float d_stats[2 * DD];     // [0,DD): sum, [DD,2DD): sumsq
__device__ float d_mu[DD];
__device__ float d_istd[DD];
__device__ float d_gsum[GG * DD];
__device__ float d_gcnt[GG];
__device__ float d_hg[GG * DD];
__device__ float d_t[GG * FT];
__device__ float d_ginv[DD];          // 1/std for gaussian basis
__device__ float d_gcoef[DD];         // 1/(a*std)

// ---------------- utility kernels ----------------
__global__ void zero_f(float* p, int n) {
    int i = blockIdx.x * blockDim.x + threadIdx.x;
    if (i < n) p[i] = 0.f;
}
__global__ void zero_i(int* p, int n) {
    int i = blockIdx.x * blockDim.x + threadIdx.x;
    if (i < n) p[i] = 0;
}

// degree counts over dst
__global__ void count_k(const int* __restrict__ dst, int* counts) {
    int e = blockIdx.x * blockDim.x + threadIdx.x;
    if (e < EE) atomicAdd(&counts[dst[e]], 1);
}
__global__ void deg_k(const int* __restrict__ counts, int* deg) {
    int n = blockIdx.x * blockDim.x + threadIdx.x;
    if (n < NN) {
        int c = counts[n] - 1;
        deg[n] = min(max(c, 0), MAXDEG - 1);
    }
}

// gaussian basis precompute
__global__ void gauss_pre_k(const float* __restrict__ g_stds, float* ginv, float* gcoef) {
    int d = blockIdx.x * blockDim.x + threadIdx.x;
    if (d < DD) {
        float s = fabsf(g_stds[d]) + 0.01f;
        float a = sqrtf(2.0f * 3.14159f);
        ginv[d] = 1.f / s;
        gcoef[d] = 1.f / (a * s);
    }
}

// scatter gaussian basis into h_in
__global__ void gauss_k(const float* __restrict__ dist, const int* __restrict__ dst,
                        const float* __restrict__ g_means,
                        const float* __restrict__ ginv, const float* __restrict__ gcoef,
                        float* hin) {
    int idx = blockIdx.x * blockDim.x + threadIdx.x;
    if (idx >= EE * DD) return;
    int e = idx / DD, d = idx - e * DD;
    float z = (dist[e] - g_means[d]) * ginv[d];
    float g = __expf(-0.5f * z * z) * gcoef[d];
    atomicAdd(&hin[dst[e] * DD + d], g);
}

// h_in *= exp(scale_param[deg])
__global__ void scale_hin_k(float* hin, const int* __restrict__ deg,
                            const float* __restrict__ scale_param) {
    int idx = blockIdx.x * blockDim.x + threadIdx.x;
    if (idx >= NN * DD) return;
    int n = idx / DD, d = idx - n * DD;
    hin[idx] *= expf(scale_param[deg[n] * DD + d]);
}

// attention-fused atom embedding: one warp per node
__global__ void attn_k(const int* __restrict__ x, const float* __restrict__ atom_emb,
                       const float* __restrict__ att_vec, float* __restrict__ fused) {
    int warp = (blockIdx.x * blockDim.x + threadIdx.x) >> 5;
    int lane = threadIdx.x & 31;
    if (warp >= NN) return;
    const int* xn = x + warp * 9;
    int ids[9];
#pragma unroll
    for (int f = 0; f < 9; f++) ids[f] = (f * 119 + xn[f]) * DD;
    float sc[9];
#pragma unroll
    for (int f = 0; f < 9; f++) {
        float p = 0.f;
        for (int d = lane; d < DD; d += 32)
            p += atom_emb[ids[f] + d] * att_vec[d];
#pragma unroll
        for (int o = 16; o > 0; o >>= 1) p += __shfl_xor_sync(0xffffffffu, p, o);
        sc[f] = p;
    }
    float m = sc[0];
#pragma unroll
    for (int f = 1; f < 9; f++) m = fmaxf(m, sc[f]);
    float s = 0.f;
#pragma unroll
    for (int f = 0; f < 9; f++) { sc[f] = __expf(sc[f] - m); s += sc[f]; }
    float inv = 1.f / s;
    for (int d = lane; d < DD; d += 32) {
        float a = 0.f;
#pragma unroll
        for (int f = 0; f < 9; f++) a += sc[f] * atom_emb[ids[f] + d];
        fused[warp * DD + d] = a * inv;
    }
}

// agg init: agg = h + e_self (self-loop edge vector, same for all nodes)
__global__ void agg_init_k(const float* __restrict__ h,
                           const float* __restrict__ e0,   // edge_emb[l,0,4,:]
                           const float* __restrict__ e1,   // edge_emb[l,1,0,:]
                           const float* __restrict__ e2,   // edge_emb[l,2,0,:]
                           float* agg) {
    int idx = blockIdx.x * blockDim.x + threadIdx.x;
    if (idx >= NN * DD) return;
    int d = idx % DD;
    agg[idx] = h[idx] + e0[d] + e1[d] + e2[d];
}

// scatter real edges: agg[dst] += h[src] + e(attr)
__global__ void scatter_k(const float* __restrict__ h,
                          const int* __restrict__ src, const int* __restrict__ dst,
                          const int* __restrict__ attr,
                          const float* __restrict__ E0, const float* __restrict__ E1,
                          const float* __restrict__ E2,
                          float* agg) {
    int idx = blockIdx.x * blockDim.x + threadIdx.x;
    if (idx >= EE * DD) return;
    int e = idx / DD, d = idx - e * DD;
    int a0 = attr[e * 3 + 0], a1 = attr[e * 3 + 1], a2 = attr[e * 3 + 2];
    float v = h[src[e] * DD + d] + E0[a0 * DD + d] + E1[a1 * DD + d] + E2[a2 * DD + d];
    atomicAdd(&agg[dst[e] * DD + d], v);
}

// ---------------- SGEMM: C[M,Nc] = act(A[M,K]@B[K,Nc] + bias + add) ----------------
template <bool RELU, bool HAS_ADD>
__global__ __launch_bounds__(256) void sgemm_k(
    const float* __restrict__ A, const float* __restrict__ B,
    const float* __restrict__ bias, const float* __restrict__ add,
    float* __restrict__ C, int M, int Nc, int K) {
    const int BM = 128, BN = 128, BK = 8;
    __shared__ float As[BK][BM + 4];
    __shared__ float Bs[BK][BN];
    int tid = threadIdx.x;
    int tx = tid % 16, ty = tid / 16;
    int bm = blockIdx.y * BM;
    int bn = blockIdx.x * BN;
    float acc[8][8];
#pragma unroll
    for (int i = 0; i < 8; i++)
#pragma unroll
        for (int j = 0; j < 8; j++) acc[i][j] = 0.f;

    for (int k0 = 0; k0 < K; k0 += BK) {
#pragma unroll
        for (int i = 0; i < 4; i++) {
            int li = tid + i * 256;
            int r = li / BK, kk = li % BK;
            int gr = bm + r, gk = k0 + kk;
            float v = 0.f;
            if (gr < M && gk < K) v = A[gr * K + gk];
            As[kk][r] = v;
        }
#pragma unroll
        for (int i = 0; i < 4; i++) {
            int li = tid + i * 256;
            int kk = li / BN, c = li % BN;
            int gc = bn + c, gk = k0 + kk;
            float v = 0.f;
            if (gk < K && gc < Nc) v = B[gk * Nc + gc];
            Bs[kk][c] = v;
        }
        __syncthreads();
#pragma unroll
        for (int kk = 0; kk < BK; kk++) {
            float ra[8], rb[8];
            // split 4+4 register tiles for conflict-free 128-bit LDS
            float4 a0 = *reinterpret_cast<const float4*>(&As[kk][ty * 4]);
            float4 a1 = *reinterpret_cast<const float4*>(&As[kk][64 + ty * 4]);
            float4 b0 = *reinterpret_cast<const float4*>(&Bs[kk][tx * 4]);
            float4 b1 = *reinterpret_cast<const float4*>(&Bs[kk][64 + tx * 4]);
            ra[0] = a0.x; ra[1] = a0.y; ra[2] = a0.z; ra[3] = a0.w;
            ra[4] = a1.x; ra[5] = a1.y; ra[6] = a1.z; ra[7] = a1.w;
            rb[0] = b0.x; rb[1] = b0.y; rb[2] = b0.z; rb[3] = b0.w;
            rb[4] = b1.x; rb[5] = b1.y; rb[6] = b1.z; rb[7] = b1.w;
#pragma unroll
            for (int i = 0; i < 8; i++)
#pragma unroll
                for (int j = 0; j < 8; j++) acc[i][j] += ra[i] * rb[j];
        }
        __syncthreads();
    }
#pragma unroll
    for (int i = 0; i < 8; i++) {
        int gr = bm + ((i < 4) ? (ty * 4 + i) : (64 + ty * 4 + i - 4));
        if (gr >= M) continue;
#pragma unroll
        for (int j = 0; j < 8; j++) {
            int gc = bn + ((j < 4) ? (tx * 4 + j) : (64 + tx * 4 + j - 4));
            if (gc >= Nc) continue;
            float v = acc[i][j] + bias[gc];
            if (HAS_ADD) v += add[gr * Nc + gc];
            if (RELU) v = fmaxf(v, 0.f);
            C[gr * Nc + gc] = v;
        }
    }
}

// ---------------- batchnorm ----------------
#define BN_RPB 128
__global__ void bn_stats_k(const float* __restrict__ h, float* stats) {
    int row0 = blockIdx.x * BN_RPB;
    int rend = min(row0 + BN_RPB, NN);
    int c0 = threadIdx.x;
    int c1 = threadIdx.x + 256;
    float s0 = 0.f, q0 = 0.f, s1 = 0.f, q1 = 0.f;
    for (int r = row0; r < rend; r++) {
        float v0 = h[r * DD + c0];
        s0 += v0; q0 += v0 * v0;
        if (c1 < DD) {
            float v1 = h[r * DD + c1];
            s1 += v1; q1 += v1 * v1;
        }
    }
    atomicAdd(&stats[c0], s0);
    atomicAdd(&stats[DD + c0], q0);
    if (c1 < DD) {
        atomicAdd(&stats[c1], s1);
        atomicAdd(&stats[DD + c1], q1);
    }
}
__global__ void bn_fin_k(const float* __restrict__ stats, float* mu, float* istd) {
    int d = blockIdx.x * blockDim.x + threadIdx.x;
    if (d < DD) {
        float m = stats[d] / (float)NN;
        float v = stats[DD + d] / (float)NN - m * m;
        v = fmaxf(v, 0.f);
        mu[d] = m;
        istd[d] = rsqrtf(v + BN_EPS);
    }
}
__global__ void bn_apply_k(float* h, const float* __restrict__ mu, const float* __restrict__ istd,
                           const float* __restrict__ gamma, const float* __restrict__ beta,
                           int relu) {
    int idx = blockIdx.x * blockDim.x + threadIdx.x;
    if (idx >= NN * DD) return;
    int d = idx % DD;
    float v = gamma[d] * (h[idx] - mu[d]) * istd[d] + beta[d];
    if (relu) v = fmaxf(v, 0.f);
    h[idx] = v;
}

// ---------------- pooling ----------------
__global__ void pool_cnt_k(const int* __restrict__ batch, float* gcnt) {
    int n = blockIdx.x * blockDim.x + threadIdx.x;
    if (n < NN) atomicAdd(&gcnt[batch[n]], 1.f);
}
__global__ void pool_sum_k(const float* __restrict__ h, const int* __restrict__ batch,
                           float* gsum) {
    int idx = blockIdx.x * blockDim.x + threadIdx.x;
    if (idx >= NN * DD) return;
    int n = idx / DD, d = idx - n * DD;
    atomicAdd(&gsum[batch[n] * DD + d], h[idx]);
}
__global__ void hg_k(const float* __restrict__ gsum, const float* __restrict__ gcnt, float* hg) {
    int idx = blockIdx.x * blockDim.x + threadIdx.x;
    if (idx >= GG * DD) return;
    int g = idx / DD;
    hg[idx] = gsum[idx] / fmaxf(gcnt[g], 1.f);
}

// ---------------- host launcher ----------------
static float* symf(const void* sym) {
    void* p = nullptr;
    cudaGetSymbolAddress(&p, sym);
    return (float*)p;
}
static int* symi(const void* sym) {
    void* p = nullptr;
    cudaGetSymbolAddress(&p, sym);
    return (int*)p;
}

static inline int cdiv(int a, int b) { return (a + b - 1) / b; }

extern "C" void kernel_launch(void* const* d_in, const int* in_sizes, int n_in,
                              void* d_out, int out_size) {
    const int* x            = (const int*)d_in[0];
    const int* edge_index   = (const int*)d_in[1];
    const int* edge_attr    = (const int*)d_in[2];
    const float* edge_dist  = (const float*)d_in[3];
    const int* batch        = (const int*)d_in[4];
    const float* atom_emb   = (const float*)d_in[5];
    const float* att_vec    = (const float*)d_in[6];
    const float* out_lin_w  = (const float*)d_in[7];
    const float* out_lin_b  = (const float*)d_in[8];
    const float* g_means    = (const float*)d_in[9];
    const float* g_stds     = (const float*)d_in[10];
    const float* scale_par  = (const float*)d_in[11];
    const float* edge_emb   = (const float*)d_in[12];
    const float* mlp_w1     = (const float*)d_in[13];
    const float* mlp_b1     = (const float*)d_in[14];
    const float* mlp_w2     = (const float*)d_in[15];
    const float* mlp_b2     = (const float*)d_in[16];
    const float* bn_gamma   = (const float*)d_in[17];
    const float* bn_beta    = (const float*)d_in[18];
    const float* feat_w     = (const float*)d_in[19];
    const float* feat_b     = (const float*)d_in[20];
    const float* ol_w1      = (const float*)d_in[21];
    const float* ol_b1      = (const float*)d_in[22];
    const float* ol_w2      = (const float*)d_in[23];
    const float* ol_b2      = (const float*)d_in[24];

    const int* e_src = edge_index;
    const int* e_dst = edge_index + EE;

    float* h      = symf(d_h);
    float* agg    = symf(d_agg);
    float* hidden = symf(d_hidden);
    float* hin    = symf(d_hin);
    int*   counts = symi(d_counts);
    int*   deg    = symi(d_deg);
    float* stats  = symf(d_stats);
    float* mu     = symf(d_mu);
    float* istd   = symf(d_istd);
    float* gsum   = symf(d_gsum);
    float* gcnt   = symf(d_gcnt);
    float* hg     = symf(d_hg);
    float* tbuf   = symf(d_t);
    float* ginv   = symf(d_ginv);
    float* gcoef  = symf(d_gcoef);

    float* out_hfeat = (float*)d_out;             // (G, FT)
    float* out_final = (float*)d_out + GG * FT;   // (G, FT/2)

    const int T = 256;

    // --- degree counts ---
    zero_i<<<cdiv(NN, T), T>>>(counts, NN);
    count_k<<<cdiv(EE, T), T>>>(e_dst, counts);
    deg_k<<<cdiv(NN, T), T>>>(counts, deg);

    // --- gaussian basis -> h_in ---
    gauss_pre_k<<<cdiv(DD, T), T>>>(g_stds, ginv, gcoef);
    zero_f<<<cdiv(NN * DD, T), T>>>(hin, NN * DD);
    gauss_k<<<cdiv(EE * DD, T), T>>>(edge_dist, e_dst, g_means, ginv, gcoef, hin);
    scale_hin_k<<<cdiv(NN * DD, T), T>>>(hin, deg, scale_par);

    // --- atom embedding attention fusion (into agg as temp) ---
    attn_k<<<cdiv(NN, 8), 256>>>(x, atom_emb, att_vec, agg);

    // --- h = fused @ out_lin_w + b + h_in ---
    {
        dim3 grid(cdiv(DD, 128), cdiv(NN, 128));
        sgemm_k<false, true><<<grid, 256>>>(agg, out_lin_w, out_lin_b, hin, h, NN, DD, DD);
    }

    // --- L message-passing layers ---
    for (int l = 0; l < LL; l++) {
        const float* E0 = edge_emb + (l * 3 + 0) * 5 * DD;
        const float* E1 = edge_emb + (l * 3 + 1) * 5 * DD;
        const float* E2 = edge_emb + (l * 3 + 2) * 5 * DD;
        // self-loop attr = [4,0,0]
        agg_init_k<<<cdiv(NN * DD, T), T>>>(h, E0 + 4 * DD, E1, E2, agg);
        scatter_k<<<cdiv(EE * DD, T), T>>>(h, e_src, e_dst, edge_attr, E0, E1, E2, agg);

        {
            dim3 g1(cdiv(D2, 128), cdiv(NN, 128));
            sgemm_k<true, false><<<g1, 256>>>(agg, mlp_w1 + l * DD * D2, mlp_b1 + l * D2,
                                              nullptr, hidden, NN, D2, DD);
            dim3 g2(cdiv(DD, 128), cdiv(NN, 128));
            sgemm_k<false, false><<<g2, 256>>>(hidden, mlp_w2 + l * D2 * DD, mlp_b2 + l * DD,
                                               nullptr, h, NN, DD, D2);
        }

        zero_f<<<cdiv(2 * DD, T), T>>>(stats, 2 * DD);
        bn_stats_k<<<cdiv(NN, BN_RPB), 256>>>(h, stats);
        bn_fin_k<<<cdiv(DD, T), T>>>(stats, mu, istd);
        bn_apply_k<<<cdiv(NN * DD, T), T>>>(h, mu, istd, bn_gamma + l * DD, bn_beta + l * DD,
                                            (l < LL - 1) ? 1 : 0);
    }

    // --- mean pooling ---
    zero_f<<<cdiv(GG * DD, T), T>>>(gsum, GG * DD);
    zero_f<<<cdiv(GG, T), T>>>(gcnt, GG);
    pool_cnt_k<<<cdiv(NN, T), T>>>(batch, gcnt);
    pool_sum_k<<<cdiv(NN * DD, T), T>>>(h, batch, gsum);
    hg_k<<<cdiv(GG * DD, T), T>>>(gsum, gcnt, hg);

    // --- head: h_feat = hg @ feat_w + feat_b (output 1) ---
    {
        dim3 g(cdiv(FT, 128), cdiv(GG, 128));
        sgemm_k<false, false><<<g, 256>>>(hg, feat_w, feat_b, nullptr, out_hfeat, GG, FT, DD);
    }
    // --- t = relu(h_feat @ ol_w1 + ol_b1) ---
    {
        dim3 g(cdiv(FT, 128), cdiv(GG, 128));
        sgemm_k<true, false><<<g, 256>>>(out_hfeat, ol_w1, ol_b1, nullptr, tbuf, GG, FT, FT);
    }
    // --- out = t @ ol_w2 + ol_b2 (output 2) ---
    {
        dim3 g(cdiv(FT / 2, 128), cdiv(GG, 128));
        sgemm_k<false, false><<<g, 256>>>(tbuf, ol_w2, ol_b2, nullptr, out_final, GG, FT / 2, FT);
    }
}

// round 4
// speedup vs baseline: 2.9642x; 2.9642x over previous
#include <cuda_runtime.h>
#include <cuda_bf16.h>
#include <math.h>
#include <stdint.h>

#define NN 100000
#define EE 200000
#define GG 2000
#define DD 300
#define D2 600
#define LL 5
#define FT 512
#define MAXDEG 4
#define BN_EPS 1e-5f

// ---------------- scratch (device globals; no allocation) ----------------
__device__ float d_h[NN * DD];
__device__ float d_agg[NN * DD];      // also "fused" before layer 0
__device__ float d_hidden[NN * D2];
__device__ float d_hin[NN * DD];
__device__ int   d_counts[NN];
__device__ int   d_cursor[NN];
__device__ int   d_rowptr[NN + 1];
__device__ int   d_part[NN];
__device__ int   d_bsum[128];
__device__ int   d_eidx[EE];
__device__ int   d_gstart[GG + 1];
__device__ float d_stats[2 * DD];
__device__ float d_mu[DD];
__device__ float d_istd[DD];
__device__ float d_hg[GG * DD];
__device__ float d_t[GG * FT];
__device__ float d_ginv[DD];
__device__ float d_gcoef[DD];
// split bf16 weights (packed bf16x2 per u32), [N][SP] with SP = ceil(K,16)/2
#define SP300 152
#define SP600 304
#define SP512 256
__device__ uint32_t d_bt0h[DD * SP300],          d_bt0l[DD * SP300];
__device__ uint32_t d_bt1h[LL * D2 * SP300],     d_bt1l[LL * D2 * SP300];
__device__ uint32_t d_bt2h[LL * DD * SP600],     d_bt2l[LL * DD * SP600];
__device__ uint32_t d_bt3h[FT * SP300],          d_bt3l[FT * SP300];
__device__ uint32_t d_bt4h[FT * SP512],          d_bt4l[FT * SP512];
__device__ uint32_t d_bt5h[(FT / 2) * SP512],    d_bt5l[(FT / 2) * SP512];

// ---------------- helpers ----------------
__device__ __forceinline__ uint32_t smem_u32(const void* p) {
    uint32_t a;
    asm("{ .reg .u64 t; cvta.to.shared.u64 t, %1; cvt.u32.u64 %0, t; }" : "=r"(a) : "l"(p));
    return a;
}
__device__ __forceinline__ void cp16(uint32_t dst, const void* src, int valid) {
    int sz = valid ? 16 : 0;
    asm volatile("cp.async.cg.shared.global [%0], [%1], 16, %2;" :: "r"(dst), "l"(src), "r"(sz) : "memory");
}
#define CP_COMMIT() asm volatile("cp.async.commit_group;" ::: "memory")
#define CP_WAIT(n)  asm volatile("cp.async.wait_group %0;" :: "n"(n) : "memory")

// split two floats into packed bf16x2 (hi) and packed bf16x2 residual (lo).
// packed low half = x0, high half = x1 (k-even in low, k-odd in high).
__device__ __forceinline__ void split2(float x0, float x1, uint32_t& hi, uint32_t& lo) {
    asm("cvt.rn.bf16x2.f32 %0, %1, %2;" : "=r"(hi) : "f"(x1), "f"(x0));
    float h0 = __uint_as_float(hi << 16);
    float h1 = __uint_as_float(hi & 0xFFFF0000u);
    float l0 = x0 - h0, l1 = x1 - h1;
    asm("cvt.rn.bf16x2.f32 %0, %1, %2;" : "=r"(lo) : "f"(l1), "f"(l0));
}
__device__ __forceinline__ void mma_bf16(float* c, const uint32_t* a, const uint32_t* b) {
    asm volatile(
        "mma.sync.aligned.m16n8k16.row.col.f32.bf16.bf16.f32 "
        "{%0,%1,%2,%3}, {%4,%5,%6,%7}, {%8,%9}, {%0,%1,%2,%3};"
        : "+f"(c[0]), "+f"(c[1]), "+f"(c[2]), "+f"(c[3])
        : "r"(a[0]), "r"(a[1]), "r"(a[2]), "r"(a[3]), "r"(b[0]), "r"(b[1]));
}

// ---------------- bf16x3 emulated-fp32 GEMM ----------------
// C[M,Nc] = act(A[M,K] @ Bt^T + bias (+ add))
// Bth/Btl: [Nc][SP] u32 (packed bf16x2 hi / lo), SP = ceil(K,16)/2, zero-padded.
// BM=128, BN=128, BK=16, 256 threads = 8 warps (2x4), warp tile 64x32.
#define AS_STRIDE 20   // floats (16 + 4 pad); row = 80B (16B aligned)
#define BS_STRIDE 12   // u32   (8 + 4 pad);  row = 48B (16B aligned)

__global__ __launch_bounds__(256) void gemm_mma_k(
    const float* __restrict__ A,
    const uint32_t* __restrict__ Bth, const uint32_t* __restrict__ Btl,
    const float* __restrict__ bias, const float* __restrict__ add,
    float* __restrict__ C, int M, int Nc, int K, int SP,
    int relu, int has_add) {
    __shared__ float    As[2][128 * AS_STRIDE];
    __shared__ uint32_t Bsh[2][128 * BS_STRIDE];
    __shared__ uint32_t Bsl[2][128 * BS_STRIDE];
    int tid = threadIdx.x, lane = tid & 31, wid = tid >> 5;
    int wm = wid & 1, wn = wid >> 1;          // 2 x 4 warp grid
    int bnc = blockIdx.x * 128;
    int bm = blockIdx.y * 128;
    int nch = (K + 15) / 16;

    float acc[4][4][4];
#pragma unroll
    for (int i = 0; i < 4; i++)
#pragma unroll
        for (int j = 0; j < 4; j++)
#pragma unroll
            for (int r = 0; r < 4; r++) acc[i][j][r] = 0.f;

    auto load_chunk = [&](int c, int s) {
        int k0 = c * 16;
        // A: 128 rows x 4 granules of 16B (16 floats)
#pragma unroll
        for (int it = 0; it < 2; it++) {
            int i = tid + it * 256;
            int r = i >> 2, g = i & 3;
            int gr = bm + r, gk = k0 + g * 4;
            cp16(smem_u32(&As[s][r * AS_STRIDE + g * 4]),
                 A + (size_t)gr * K + gk, (gr < M) && (gk < K));
        }
        // B hi+lo: 128 rows x 2 granules each (8 u32 = 16 k)
        {
            int r = tid >> 1, g = tid & 1;
            int br = bnc + r;
            int gu = (k0 >> 1) + g * 4;
            int valid = br < Nc;
            cp16(smem_u32(&Bsh[s][r * BS_STRIDE + g * 4]), Bth + (size_t)br * SP + gu, valid);
            cp16(smem_u32(&Bsl[s][r * BS_STRIDE + g * 4]), Btl + (size_t)br * SP + gu, valid);
        }
    };

    load_chunk(0, 0);
    CP_COMMIT();

    int row = lane >> 2, qc = lane & 3;
    int kb = qc * 2;
    for (int c = 0; c < nch; c++) {
        if (c + 1 < nch) {
            load_chunk(c + 1, (c + 1) & 1);
            CP_COMMIT();
            CP_WAIT(1);
        } else {
            CP_WAIT(0);
        }
        __syncthreads();
        int s = c & 1;
        // B fragments (live across mt loop)
        uint32_t bfh[4][2], bfl[4][2];
#pragma unroll
        for (int nt = 0; nt < 4; nt++) {
            int n = wn * 32 + nt * 8 + row;
            bfh[nt][0] = Bsh[s][n * BS_STRIDE + qc];
            bfh[nt][1] = Bsh[s][n * BS_STRIDE + 4 + qc];
            bfl[nt][0] = Bsl[s][n * BS_STRIDE + qc];
            bfl[nt][1] = Bsl[s][n * BS_STRIDE + 4 + qc];
        }
#pragma unroll
        for (int mt = 0; mt < 4; mt++) {
            int r0 = wm * 64 + mt * 16 + row;
            float2 p0 = *reinterpret_cast<const float2*>(&As[s][r0 * AS_STRIDE + kb]);
            float2 p1 = *reinterpret_cast<const float2*>(&As[s][(r0 + 8) * AS_STRIDE + kb]);
            float2 p2 = *reinterpret_cast<const float2*>(&As[s][r0 * AS_STRIDE + kb + 8]);
            float2 p3 = *reinterpret_cast<const float2*>(&As[s][(r0 + 8) * AS_STRIDE + kb + 8]);
            uint32_t ah[4], al[4];
            split2(p0.x, p0.y, ah[0], al[0]);
            split2(p1.x, p1.y, ah[1], al[1]);
            split2(p2.x, p2.y, ah[2], al[2]);
            split2(p3.x, p3.y, ah[3], al[3]);
#pragma unroll
            for (int nt = 0; nt < 4; nt++) {
                mma_bf16(acc[mt][nt], ah, bfl[nt]);
                mma_bf16(acc[mt][nt], al, bfh[nt]);
                mma_bf16(acc[mt][nt], ah, bfh[nt]);
            }
        }
        __syncthreads();
    }

    // epilogue
#pragma unroll
    for (int mt = 0; mt < 4; mt++) {
#pragma unroll
        for (int nt = 0; nt < 4; nt++) {
#pragma unroll
            for (int half = 0; half < 2; half++) {
                int gr = bm + wm * 64 + mt * 16 + row + half * 8;
                if (gr >= M) continue;
#pragma unroll
                for (int j = 0; j < 2; j++) {
                    int gc = bnc + wn * 32 + nt * 8 + qc * 2 + j;
                    if (gc >= Nc) continue;
                    float v = acc[mt][nt][half * 2 + j] + bias[gc];
                    if (has_add) v += add[(size_t)gr * Nc + gc];
                    if (relu) v = fmaxf(v, 0.f);
                    C[(size_t)gr * Nc + gc] = v;
                }
            }
        }
    }
}

// ---------------- weight transpose + bf16 hi/lo split ----------------
// w is [K][N] row-major; outputs [N][SP] u32 (k-pairs packed), zero-padded.
__global__ void prep_split_k(const float* __restrict__ w, uint32_t* bth, uint32_t* btl,
                             int K, int N, int SP) {
    int idx = blockIdx.x * blockDim.x + threadIdx.x;
    if (idx >= N * SP) return;
    int n = idx / SP, ku = idx % SP;
    int k0 = ku * 2, k1 = k0 + 1;
    float x0 = (k0 < K) ? w[(size_t)k0 * N + n] : 0.f;
    float x1 = (k1 < K) ? w[(size_t)k1 * N + n] : 0.f;
    uint32_t hi, lo;
    split2(x0, x1, hi, lo);
    bth[idx] = hi;
    btl[idx] = lo;
}

// ---------------- misc ----------------
__global__ void zero_i(int* p, int n) {
    int i = blockIdx.x * blockDim.x + threadIdx.x;
    if (i < n) p[i] = 0;
}
__global__ void count_k(const int* __restrict__ dst, int* counts) {
    int e = blockIdx.x * blockDim.x + threadIdx.x;
    if (e < EE) atomicAdd(&counts[dst[e]], 1);
}

// ---------------- CSR build ----------------
__global__ void scan1_k(const int* __restrict__ counts, int* part, int* bsum) {
    __shared__ int sh[1024];
    int tid = threadIdx.x;
    int i = blockIdx.x * 1024 + tid;
    int v = (i < NN) ? counts[i] : 0;
    sh[tid] = v;
    __syncthreads();
#pragma unroll
    for (int off = 1; off < 1024; off <<= 1) {
        int t = (tid >= off) ? sh[tid - off] : 0;
        __syncthreads();
        sh[tid] += t;
        __syncthreads();
    }
    if (i < NN) part[i] = sh[tid] - v;   // exclusive
    if (tid == 1023) bsum[blockIdx.x] = sh[1023];
}
__global__ void scan2_k(int* bsum, int nb) {
    if (threadIdx.x == 0 && blockIdx.x == 0) {
        int run = 0;
        for (int b = 0; b < nb; b++) {
            int t = bsum[b];
            bsum[b] = run;
            run += t;
        }
    }
}
__global__ void scan3_k(const int* __restrict__ part, const int* __restrict__ bsum, int* rowptr) {
    int i = blockIdx.x * blockDim.x + threadIdx.x;
    if (i < NN) rowptr[i] = part[i] + bsum[i >> 10];
    if (i == 0) rowptr[NN] = EE;
}
__global__ void fill_k(const int* __restrict__ dst, const int* __restrict__ rowptr,
                       int* cursor, int* eidx) {
    int e = blockIdx.x * blockDim.x + threadIdx.x;
    if (e >= EE) return;
    int d = dst[e];
    int pos = atomicAdd(&cursor[d], 1);
    eidx[rowptr[d] + pos] = e;
}

// ---------------- gaussian basis (CSR gather, folds degree scaling) ----------------
__global__ void gauss_pre_k(const float* __restrict__ g_stds, float* ginv, float* gcoef) {
    int d = blockIdx.x * blockDim.x + threadIdx.x;
    if (d < DD) {
        float s = fabsf(g_stds[d]) + 0.01f;
        float a = sqrtf(2.0f * 3.14159f);
        ginv[d] = 1.f / s;
        gcoef[d] = 1.f / (a * s);
    }
}
__global__ void gauss_csr_k(const float* __restrict__ dist, const int* __restrict__ rowptr,
                            const int* __restrict__ eidx,
                            const float* __restrict__ g_means,
                            const float* __restrict__ ginv, const float* __restrict__ gcoef,
                            const float* __restrict__ scale_param, float* __restrict__ hin) {
    int n = (blockIdx.x * blockDim.x + threadIdx.x) >> 5;
    int lane = threadIdx.x & 31;
    if (n >= NN) return;
    int beg = rowptr[n], end = rowptr[n + 1];
    int degc = min(max(end - beg - 1, 0), MAXDEG - 1);
    float gm[10], gi[10], gc[10], acc[10];
#pragma unroll
    for (int c = 0; c < 10; c++) {
        int d = c * 32 + lane;
        acc[c] = 0.f;
        if (d < DD) { gm[c] = g_means[d]; gi[c] = ginv[d]; gc[c] = gcoef[d]; }
    }
    for (int j = beg; j < end; j++) {
        float de = dist[eidx[j]];
#pragma unroll
        for (int c = 0; c < 10; c++) {
            int d = c * 32 + lane;
            if (d < DD) {
                float z = (de - gm[c]) * gi[c];
                acc[c] += __expf(-0.5f * z * z) * gc[c];
            }
        }
    }
    const float* sp = scale_param + degc * DD;
#pragma unroll
    for (int c = 0; c < 10; c++) {
        int d = c * 32 + lane;
        if (d < DD) hin[(size_t)n * DD + d] = acc[c] * expf(sp[d]);
    }
}

// ---------------- attention fusion ----------------
__global__ void attn_k(const int* __restrict__ x, const float* __restrict__ atom_emb,
                       const float* __restrict__ att_vec, float* __restrict__ fused) {
    int warp = (blockIdx.x * blockDim.x + threadIdx.x) >> 5;
    int lane = threadIdx.x & 31;
    if (warp >= NN) return;
    const int* xn = x + warp * 9;
    int ids[9];
#pragma unroll
    for (int f = 0; f < 9; f++) ids[f] = (f * 119 + xn[f]) * DD;
    float sc[9];
#pragma unroll
    for (int f = 0; f < 9; f++) {
        float p = 0.f;
        for (int d = lane; d < DD; d += 32)
            p += atom_emb[ids[f] + d] * att_vec[d];
#pragma unroll
        for (int o = 16; o > 0; o >>= 1) p += __shfl_xor_sync(0xffffffffu, p, o);
        sc[f] = p;
    }
    float m = sc[0];
#pragma unroll
    for (int f = 1; f < 9; f++) m = fmaxf(m, sc[f]);
    float s = 0.f;
#pragma unroll
    for (int f = 0; f < 9; f++) { sc[f] = __expf(sc[f] - m); s += sc[f]; }
    float inv = 1.f / s;
    for (int d = lane; d < DD; d += 32) {
        float a = 0.f;
#pragma unroll
        for (int f = 0; f < 9; f++) a += sc[f] * atom_emb[ids[f] + d];
        fused[(size_t)warp * DD + d] = a * inv;
    }
}

// ---------------- CSR aggregation (incl. self loop) ----------------
__global__ void gather_k(const float* __restrict__ h,
                         const int* __restrict__ rowptr, const int* __restrict__ eidx,
                         const int* __restrict__ src, const int* __restrict__ attr,
                         const float* __restrict__ E0, const float* __restrict__ E1,
                         const float* __restrict__ E2,
                         float* __restrict__ agg) {
    int n = (blockIdx.x * blockDim.x + threadIdx.x) >> 5;
    int lane = threadIdx.x & 31;
    if (n >= NN) return;
    int beg = rowptr[n], end = rowptr[n + 1];
    float acc[10];
    const float* es0 = E0 + 4 * DD;   // self-loop attr [4,0,0]
#pragma unroll
    for (int c = 0; c < 10; c++) {
        int d = c * 32 + lane;
        if (d < DD) acc[c] = h[(size_t)n * DD + d] + es0[d] + E1[d] + E2[d];
        else acc[c] = 0.f;
    }
    for (int j = beg; j < end; j++) {
        int e = eidx[j];
        int s = src[e];
        int a0 = attr[e * 3 + 0], a1 = attr[e * 3 + 1], a2 = attr[e * 3 + 2];
        const float* hs = h + (size_t)s * DD;
        const float* p0 = E0 + a0 * DD;
        const float* p1 = E1 + a1 * DD;
        const float* p2 = E2 + a2 * DD;
#pragma unroll
        for (int c = 0; c < 10; c++) {
            int d = c * 32 + lane;
            if (d < DD) acc[c] += hs[d] + p0[d] + p1[d] + p2[d];
        }
    }
#pragma unroll
    for (int c = 0; c < 10; c++) {
        int d = c * 32 + lane;
        if (d < DD) agg[(size_t)n * DD + d] = acc[c];
    }
}

// ---------------- batchnorm ----------------
#define BN_RPB 128
__global__ void bn_stats_k(const float* __restrict__ h, float* stats) {
    int row0 = blockIdx.x * BN_RPB;
    int rend = min(row0 + BN_RPB, NN);
    int c0 = threadIdx.x;
    int c1 = threadIdx.x + 256;
    float s0 = 0.f, q0 = 0.f, s1 = 0.f, q1 = 0.f;
    for (int r = row0; r < rend; r++) {
        float v0 = h[(size_t)r * DD + c0];
        s0 += v0; q0 += v0 * v0;
        if (c1 < DD) {
            float v1 = h[(size_t)r * DD + c1];
            s1 += v1; q1 += v1 * v1;
        }
    }
    atomicAdd(&stats[c0], s0);
    atomicAdd(&stats[DD + c0], q0);
    if (c1 < DD) {
        atomicAdd(&stats[c1], s1);
        atomicAdd(&stats[DD + c1], q1);
    }
}
__global__ void bn_fin_k(const float* __restrict__ stats, float* mu, float* istd, float* stats_z) {
    int d = blockIdx.x * blockDim.x + threadIdx.x;
    if (d < DD) {
        float m = stats[d] / (float)NN;
        float v = stats[DD + d] / (float)NN - m * m;
        v = fmaxf(v, 0.f);
        mu[d] = m;
        istd[d] = rsqrtf(v + BN_EPS);
        stats_z[d] = 0.f;            // re-zero for next layer / next replay
        stats_z[DD + d] = 0.f;
    }
}
__global__ void bn_apply_k(float* h, const float* __restrict__ mu, const float* __restrict__ istd,
                           const float* __restrict__ gamma, const float* __restrict__ beta,
                           int relu) {
    int idx = blockIdx.x * blockDim.x + threadIdx.x;
    if (idx >= NN * DD) return;
    int d = idx % DD;
    float v = gamma[d] * (h[idx] - mu[d]) * istd[d] + beta[d];
    if (relu) v = fmaxf(v, 0.f);
    h[idx] = v;
}

// ---------------- pooling (batch is sorted) ----------------
__global__ void gstart_k(const int* __restrict__ batch, int* gstart) {
    int g = blockIdx.x * blockDim.x + threadIdx.x;
    if (g > GG) return;
    int lo = 0, hi = NN;
    while (lo < hi) {
        int mid = (lo + hi) >> 1;
        if (batch[mid] < g) lo = mid + 1; else hi = mid;
    }
    gstart[g] = lo;
}
__global__ void pool_k(const float* __restrict__ h, const int* __restrict__ gstart,
                       float* __restrict__ hg) {
    int g = blockIdx.x;
    int c = threadIdx.x;
    if (c >= DD) return;
    int s = gstart[g], e = gstart[g + 1];
    float a = 0.f;
    for (int r = s; r < e; r++) a += h[(size_t)r * DD + c];
    float cnt = (float)(e - s);
    hg[(size_t)g * DD + c] = a / fmaxf(cnt, 1.f);
}

// ---------------- host ----------------
static float* symf(const void* sym) { void* p = nullptr; cudaGetSymbolAddress(&p, sym); return (float*)p; }
static int* symi(const void* sym) { void* p = nullptr; cudaGetSymbolAddress(&p, sym); return (int*)p; }
static uint32_t* symu(const void* sym) { void* p = nullptr; cudaGetSymbolAddress(&p, sym); return (uint32_t*)p; }
static inline int cdiv(int a, int b) { return (a + b - 1) / b; }

extern "C" void kernel_launch(void* const* d_in, const int* in_sizes, int n_in,
                              void* d_out, int out_size) {
    const int* x            = (const int*)d_in[0];
    const int* edge_index   = (const int*)d_in[1];
    const int* edge_attr    = (const int*)d_in[2];
    const float* edge_dist  = (const float*)d_in[3];
    const int* batch        = (const int*)d_in[4];
    const float* atom_emb   = (const float*)d_in[5];
    const float* att_vec    = (const float*)d_in[6];
    const float* out_lin_w  = (const float*)d_in[7];
    const float* out_lin_b  = (const float*)d_in[8];
    const float* g_means    = (const float*)d_in[9];
    const float* g_stds     = (const float*)d_in[10];
    const float* scale_par  = (const float*)d_in[11];
    const float* edge_emb   = (const float*)d_in[12];
    const float* mlp_w1     = (const float*)d_in[13];
    const float* mlp_b1     = (const float*)d_in[14];
    const float* mlp_w2     = (const float*)d_in[15];
    const float* mlp_b2     = (const float*)d_in[16];
    const float* bn_gamma   = (const float*)d_in[17];
    const float* bn_beta    = (const float*)d_in[18];
    const float* feat_w     = (const float*)d_in[19];
    const float* feat_b     = (const float*)d_in[20];
    const float* ol_w1      = (const float*)d_in[21];
    const float* ol_b1      = (const float*)d_in[22];
    const float* ol_w2      = (const float*)d_in[23];
    const float* ol_b2      = (const float*)d_in[24];

    const int* e_src = edge_index;
    const int* e_dst = edge_index + EE;

    float* h      = symf(d_h);
    float* agg    = symf(d_agg);
    float* hidden = symf(d_hidden);
    float* hin    = symf(d_hin);
    int*   counts = symi(d_counts);
    int*   cursor = symi(d_cursor);
    int*   rowptr = symi(d_rowptr);
    int*   part   = symi(d_part);
    int*   bsum   = symi(d_bsum);
    int*   eidx   = symi(d_eidx);
    int*   gstart = symi(d_gstart);
    float* stats  = symf(d_stats);
    float* mu     = symf(d_mu);
    float* istd   = symf(d_istd);
    float* hg     = symf(d_hg);
    float* tbuf   = symf(d_t);
    float* ginv   = symf(d_ginv);
    float* gcoef  = symf(d_gcoef);
    uint32_t* bt0h = symu(d_bt0h), *bt0l = symu(d_bt0l);
    uint32_t* bt1h = symu(d_bt1h), *bt1l = symu(d_bt1l);
    uint32_t* bt2h = symu(d_bt2h), *bt2l = symu(d_bt2l);
    uint32_t* bt3h = symu(d_bt3h), *bt3l = symu(d_bt3l);
    uint32_t* bt4h = symu(d_bt4h), *bt4l = symu(d_bt4l);
    uint32_t* bt5h = symu(d_bt5h), *bt5l = symu(d_bt5l);

    float* out_hfeat = (float*)d_out;
    float* out_final = (float*)d_out + GG * FT;

    const int T = 256;

    // --- weight transposes + bf16 hi/lo split ---
    prep_split_k<<<cdiv(DD * SP300, T), T>>>(out_lin_w, bt0h, bt0l, DD, DD, SP300);
    for (int l = 0; l < LL; l++) {
        prep_split_k<<<cdiv(D2 * SP300, T), T>>>(mlp_w1 + (size_t)l * DD * D2,
                                                 bt1h + (size_t)l * D2 * SP300,
                                                 bt1l + (size_t)l * D2 * SP300, DD, D2, SP300);
        prep_split_k<<<cdiv(DD * SP600, T), T>>>(mlp_w2 + (size_t)l * D2 * DD,
                                                 bt2h + (size_t)l * DD * SP600,
                                                 bt2l + (size_t)l * DD * SP600, D2, DD, SP600);
    }
    prep_split_k<<<cdiv(FT * SP300, T), T>>>(feat_w, bt3h, bt3l, DD, FT, SP300);
    prep_split_k<<<cdiv(FT * SP512, T), T>>>(ol_w1, bt4h, bt4l, FT, FT, SP512);
    prep_split_k<<<cdiv((FT / 2) * SP512, T), T>>>(ol_w2, bt5h, bt5l, FT, FT / 2, SP512);

    // --- CSR build over dst ---
    zero_i<<<cdiv(NN, T), T>>>(counts, NN);
    count_k<<<cdiv(EE, T), T>>>(e_dst, counts);
    {
        int nb = cdiv(NN, 1024);
        scan1_k<<<nb, 1024>>>(counts, part, bsum);
        scan2_k<<<1, 32>>>(bsum, nb);
        scan3_k<<<cdiv(NN, T), T>>>(part, bsum, rowptr);
    }
    zero_i<<<cdiv(NN, T), T>>>(cursor, NN);
    fill_k<<<cdiv(EE, T), T>>>(e_dst, rowptr, cursor, eidx);

    // --- gaussian basis -> h_in (degree scaling folded) ---
    gauss_pre_k<<<cdiv(DD, T), T>>>(g_stds, ginv, gcoef);
    gauss_csr_k<<<cdiv(NN * 32, T), T>>>(edge_dist, rowptr, eidx, g_means, ginv, gcoef,
                                         scale_par, hin);

    // --- atom embedding attention fusion (into agg) ---
    attn_k<<<cdiv(NN * 32, T), T>>>(x, atom_emb, att_vec, agg);

    // --- h = fused @ out_lin_w + b + h_in ---
    {
        dim3 grid(cdiv(DD, 128), cdiv(NN, 128));
        gemm_mma_k<<<grid, 256>>>(agg, bt0h, bt0l, out_lin_b, hin, h,
                                  NN, DD, DD, SP300, 0, 1);
    }

    // --- L message-passing layers ---
    for (int l = 0; l < LL; l++) {
        const float* E0 = edge_emb + (size_t)(l * 3 + 0) * 5 * DD;
        const float* E1 = edge_emb + (size_t)(l * 3 + 1) * 5 * DD;
        const float* E2 = edge_emb + (size_t)(l * 3 + 2) * 5 * DD;
        gather_k<<<cdiv(NN * 32, T), T>>>(h, rowptr, eidx, e_src, edge_attr, E0, E1, E2, agg);
        {
            dim3 g1(cdiv(D2, 128), cdiv(NN, 128));
            gemm_mma_k<<<g1, 256>>>(agg, bt1h + (size_t)l * D2 * SP300,
                                    bt1l + (size_t)l * D2 * SP300,
                                    mlp_b1 + l * D2, nullptr, hidden,
                                    NN, D2, DD, SP300, 1, 0);
            dim3 g2(cdiv(DD, 128), cdiv(NN, 128));
            gemm_mma_k<<<g2, 256>>>(hidden, bt2h + (size_t)l * DD * SP600,
                                    bt2l + (size_t)l * DD * SP600,
                                    mlp_b2 + l * DD, nullptr, h,
                                    NN, DD, D2, SP600, 0, 0);
        }
        bn_stats_k<<<cdiv(NN, BN_RPB), 256>>>(h, stats);
        bn_fin_k<<<cdiv(DD, T), T>>>(stats, mu, istd, stats);
        bn_apply_k<<<cdiv(NN * DD, T), T>>>(h, mu, istd, bn_gamma + l * DD, bn_beta + l * DD,
                                            (l < LL - 1) ? 1 : 0);
    }

    // --- mean pooling (batch sorted -> segment reduce) ---
    gstart_k<<<cdiv(GG + 1, T), T>>>(batch, gstart);
    pool_k<<<GG, 320>>>(h, gstart, hg);

    // --- head ---
    {
        dim3 g(cdiv(FT, 128), cdiv(GG, 128));
        gemm_mma_k<<<g, 256>>>(hg, bt3h, bt3l, feat_b, nullptr, out_hfeat,
                               GG, FT, DD, SP300, 0, 0);
    }
    {
        dim3 g(cdiv(FT, 128), cdiv(GG, 128));
        gemm_mma_k<<<g, 256>>>(out_hfeat, bt4h, bt4l, ol_b1, nullptr, tbuf,
                               GG, FT, FT, SP512, 1, 0);
    }
    {
        dim3 g(cdiv(FT / 2, 128), cdiv(GG, 128));
        gemm_mma_k<<<g, 256>>>(tbuf, bt5h, bt5l, ol_b2, nullptr, out_final,
                               GG, FT / 2, FT, SP512, 0, 0);
    }
}

// round 5
// speedup vs baseline: 3.1576x; 1.0653x over previous
#include <cuda_runtime.h>
#include <cuda_bf16.h>
#include <math.h>
#include <stdint.h>

#define NN 100000
#define EE 200000
#define GG 2000
#define DD 300
#define D2 600
#define LL 5
#define FT 512
#define MAXDEG 4
#define BN_EPS 1e-5f

#define SP300 152
#define SP600 304
#define SP512 256

// ---------------- scratch (device globals; no allocation) ----------------
__device__ float d_h[NN * DD];
__device__ float d_hin[NN * DD];
__device__ int   d_counts[NN];
__device__ int   d_cursor[NN];
__device__ int   d_rowptr[NN + 1];
__device__ int   d_part[NN];
__device__ int   d_bsum[128];
__device__ int   d_eidx[EE];
__device__ int   d_gstart[GG + 1];
__device__ float d_stats[2 * DD];
__device__ float d_mu[DD];
__device__ float d_istd[DD];
__device__ float d_ginv[DD];
__device__ float d_gcoef[DD];
// split activations (packed bf16x2 hi/lo)
__device__ uint32_t d_aggh[NN * SP300], d_aggl[NN * SP300];   // also "fused"
__device__ uint32_t d_hidh[NN * SP600], d_hidl[NN * SP600];
__device__ uint32_t d_hgh[GG * SP300],  d_hgl[GG * SP300];
__device__ uint32_t d_hfh[GG * SP512],  d_hfl[GG * SP512];
__device__ uint32_t d_tbh[GG * SP512],  d_tbl[GG * SP512];
// split weights [N][SP]
__device__ uint32_t d_bt0h[DD * SP300],          d_bt0l[DD * SP300];
__device__ uint32_t d_bt1h[LL * D2 * SP300],     d_bt1l[LL * D2 * SP300];
__device__ uint32_t d_bt2h[LL * DD * SP600],     d_bt2l[LL * DD * SP600];
__device__ uint32_t d_bt3h[FT * SP300],          d_bt3l[FT * SP300];
__device__ uint32_t d_bt4h[FT * SP512],          d_bt4l[FT * SP512];
__device__ uint32_t d_bt5h[(FT / 2) * SP512],    d_bt5l[(FT / 2) * SP512];

// ---------------- helpers ----------------
__device__ __forceinline__ uint32_t smem_u32(const void* p) {
    uint32_t a;
    asm("{ .reg .u64 t; cvta.to.shared.u64 t, %1; cvt.u32.u64 %0, t; }" : "=r"(a) : "l"(p));
    return a;
}
__device__ __forceinline__ void cp16(uint32_t dst, const void* src, int valid) {
    int sz = valid ? 16 : 0;
    asm volatile("cp.async.cg.shared.global [%0], [%1], 16, %2;" :: "r"(dst), "l"(src), "r"(sz) : "memory");
}
#define CP_COMMIT() asm volatile("cp.async.commit_group;" ::: "memory")
#define CP_WAIT(n)  asm volatile("cp.async.wait_group %0;" :: "n"(n) : "memory")

__device__ __forceinline__ void split2(float x0, float x1, uint32_t& hi, uint32_t& lo) {
    asm("cvt.rn.bf16x2.f32 %0, %1, %2;" : "=r"(hi) : "f"(x1), "f"(x0));
    float h0 = __uint_as_float(hi << 16);
    float h1 = __uint_as_float(hi & 0xFFFF0000u);
    float l0 = x0 - h0, l1 = x1 - h1;
    asm("cvt.rn.bf16x2.f32 %0, %1, %2;" : "=r"(lo) : "f"(l1), "f"(l0));
}
__device__ __forceinline__ void mma_bf16(float* c, const uint32_t* a, const uint32_t* b) {
    asm volatile(
        "mma.sync.aligned.m16n8k16.row.col.f32.bf16.bf16.f32 "
        "{%0,%1,%2,%3}, {%4,%5,%6,%7}, {%8,%9}, {%0,%1,%2,%3};"
        : "+f"(c[0]), "+f"(c[1]), "+f"(c[2]), "+f"(c[3])
        : "r"(a[0]), "r"(a[1]), "r"(a[2]), "r"(a[3]), "r"(b[0]), "r"(b[1]));
}

// ---------------- bf16x3 emulated-fp32 GEMM, pre-split operands ----------------
// C[M,Nc] = act(A @ B^T + bias (+ add)); A: [M][SP] u32 hi/lo, B: [Nc][SP] u32 hi/lo.
// BM=128, BN=128, BK=16 (8 u32), 256 threads = 8 warps (2x4), warp tile 64x32.
#define SS 12            // smem row stride in u32 (8 + 4 pad) -> conflict-free
#define SM_CH 1536       // 128 * SS
#define GEMM_SMEM (4 * SM_CH * 2 * 4)   // 4 arrays x 2 stages x 1536 u32 x 4B = 49152

__global__ __launch_bounds__(256) void gemm_mma_k(
    const uint32_t* __restrict__ Ah, const uint32_t* __restrict__ Al,
    const uint32_t* __restrict__ Bh, const uint32_t* __restrict__ Bl,
    const float* __restrict__ bias, const float* __restrict__ add,
    float* __restrict__ C, uint32_t* __restrict__ Oh, uint32_t* __restrict__ Ol,
    int M, int Nc, int SP, int SPo, int relu, int has_add) {
    extern __shared__ uint32_t sm[];
    // layout: [stage][arr(Ah,Al,Bh,Bl)][SM_CH]
    int tid = threadIdx.x, lane = tid & 31, wid = tid >> 5;
    int wm = wid & 1, wn = wid >> 1;
    int bnc = blockIdx.x * 128;
    int bm = blockIdx.y * 128;
    int nch = SP >> 3;

    float acc[4][4][4];
#pragma unroll
    for (int i = 0; i < 4; i++)
#pragma unroll
        for (int j = 0; j < 4; j++)
#pragma unroll
            for (int r = 0; r < 4; r++) acc[i][j][r] = 0.f;

    int lr = tid >> 1, lg = tid & 1;
    auto load_chunk = [&](int c, int s) {
        uint32_t* base = sm + s * 4 * SM_CH;
        int gu = c * 8 + lg * 4;
        int gr = bm + lr, br = bnc + lr;
        uint32_t off = smem_u32(base + lr * SS + lg * 4);
        int va = gr < M, vb = br < Nc;
        cp16(off,                     Ah + (size_t)gr * SP + gu, va);
        cp16(off + SM_CH * 4,         Al + (size_t)gr * SP + gu, va);
        cp16(off + 2 * SM_CH * 4,     Bh + (size_t)br * SP + gu, vb);
        cp16(off + 3 * SM_CH * 4,     Bl + (size_t)br * SP + gu, vb);
    };

    load_chunk(0, 0);
    CP_COMMIT();

    int row = lane >> 2, qc = lane & 3;
    for (int c = 0; c < nch; c++) {
        if (c + 1 < nch) {
            load_chunk(c + 1, (c + 1) & 1);
            CP_COMMIT();
            CP_WAIT(1);
        } else {
            CP_WAIT(0);
        }
        __syncthreads();
        uint32_t* base = sm + (c & 1) * 4 * SM_CH;
        uint32_t* sAh = base;
        uint32_t* sAl = base + SM_CH;
        uint32_t* sBh = base + 2 * SM_CH;
        uint32_t* sBl = base + 3 * SM_CH;
        uint32_t bfh[4][2], bfl[4][2];
#pragma unroll
        for (int nt = 0; nt < 4; nt++) {
            int n = wn * 32 + nt * 8 + row;
            bfh[nt][0] = sBh[n * SS + qc];
            bfh[nt][1] = sBh[n * SS + 4 + qc];
            bfl[nt][0] = sBl[n * SS + qc];
            bfl[nt][1] = sBl[n * SS + 4 + qc];
        }
#pragma unroll
        for (int mt = 0; mt < 4; mt++) {
            int r0 = wm * 64 + mt * 16 + row;
            uint32_t ah[4], al[4];
            ah[0] = sAh[r0 * SS + qc];       ah[1] = sAh[(r0 + 8) * SS + qc];
            ah[2] = sAh[r0 * SS + 4 + qc];   ah[3] = sAh[(r0 + 8) * SS + 4 + qc];
            al[0] = sAl[r0 * SS + qc];       al[1] = sAl[(r0 + 8) * SS + qc];
            al[2] = sAl[r0 * SS + 4 + qc];   al[3] = sAl[(r0 + 8) * SS + 4 + qc];
#pragma unroll
            for (int nt = 0; nt < 4; nt++) {
                mma_bf16(acc[mt][nt], ah, bfl[nt]);
                mma_bf16(acc[mt][nt], al, bfh[nt]);
                mma_bf16(acc[mt][nt], ah, bfh[nt]);
            }
        }
        __syncthreads();
    }

    // epilogue (all Nc are even -> pair guard on gc0 suffices)
#pragma unroll
    for (int mt = 0; mt < 4; mt++) {
#pragma unroll
        for (int nt = 0; nt < 4; nt++) {
#pragma unroll
            for (int half = 0; half < 2; half++) {
                int gr = bm + wm * 64 + mt * 16 + row + half * 8;
                if (gr >= M) continue;
                int gc0 = bnc + wn * 32 + nt * 8 + qc * 2;
                if (gc0 >= Nc) continue;
                float v0 = acc[mt][nt][half * 2 + 0] + bias[gc0];
                float v1 = acc[mt][nt][half * 2 + 1] + bias[gc0 + 1];
                if (has_add) {
                    v0 += add[(size_t)gr * Nc + gc0];
                    v1 += add[(size_t)gr * Nc + gc0 + 1];
                }
                if (relu) { v0 = fmaxf(v0, 0.f); v1 = fmaxf(v1, 0.f); }
                if (C) {
                    C[(size_t)gr * Nc + gc0] = v0;
                    C[(size_t)gr * Nc + gc0 + 1] = v1;
                }
                if (Oh) {
                    uint32_t hi, lo;
                    split2(v0, v1, hi, lo);
                    int p = gc0 >> 1;
                    Oh[(size_t)gr * SPo + p] = hi;
                    Ol[(size_t)gr * SPo + p] = lo;
                }
            }
        }
    }
}

// ---------------- weight transpose + bf16 hi/lo split ----------------
__global__ void prep_split_k(const float* __restrict__ w, uint32_t* bth, uint32_t* btl,
                             int K, int N, int SP) {
    int idx = blockIdx.x * blockDim.x + threadIdx.x;
    if (idx >= N * SP) return;
    int n = idx / SP, ku = idx % SP;
    int k0 = ku * 2, k1 = k0 + 1;
    float x0 = (k0 < K) ? w[(size_t)k0 * N + n] : 0.f;
    float x1 = (k1 < K) ? w[(size_t)k1 * N + n] : 0.f;
    uint32_t hi, lo;
    split2(x0, x1, hi, lo);
    bth[idx] = hi;
    btl[idx] = lo;
}

// ---------------- misc ----------------
__global__ void zero_i(int* p, int n) {
    int i = blockIdx.x * blockDim.x + threadIdx.x;
    if (i < n) p[i] = 0;
}
__global__ void count_k(const int* __restrict__ dst, int* counts) {
    int e = blockIdx.x * blockDim.x + threadIdx.x;
    if (e < EE) atomicAdd(&counts[dst[e]], 1);
}

// ---------------- CSR build ----------------
__global__ void scan1_k(const int* __restrict__ counts, int* part, int* bsum) {
    __shared__ int sh[1024];
    int tid = threadIdx.x;
    int i = blockIdx.x * 1024 + tid;
    int v = (i < NN) ? counts[i] : 0;
    sh[tid] = v;
    __syncthreads();
#pragma unroll
    for (int off = 1; off < 1024; off <<= 1) {
        int t = (tid >= off) ? sh[tid - off] : 0;
        __syncthreads();
        sh[tid] += t;
        __syncthreads();
    }
    if (i < NN) part[i] = sh[tid] - v;
    if (tid == 1023) bsum[blockIdx.x] = sh[1023];
}
__global__ void scan2_k(int* bsum, int nb) {
    if (threadIdx.x == 0 && blockIdx.x == 0) {
        int run = 0;
        for (int b = 0; b < nb; b++) { int t = bsum[b]; bsum[b] = run; run += t; }
    }
}
__global__ void scan3_k(const int* __restrict__ part, const int* __restrict__ bsum, int* rowptr) {
    int i = blockIdx.x * blockDim.x + threadIdx.x;
    if (i < NN) rowptr[i] = part[i] + bsum[i >> 10];
    if (i == 0) rowptr[NN] = EE;
}
__global__ void fill_k(const int* __restrict__ dst, const int* __restrict__ rowptr,
                       int* cursor, int* eidx) {
    int e = blockIdx.x * blockDim.x + threadIdx.x;
    if (e >= EE) return;
    int d = dst[e];
    int pos = atomicAdd(&cursor[d], 1);
    eidx[rowptr[d] + pos] = e;
}

// ---------------- gaussian basis ----------------
__global__ void gauss_pre_k(const float* __restrict__ g_stds, float* ginv, float* gcoef) {
    int d = blockIdx.x * blockDim.x + threadIdx.x;
    if (d < DD) {
        float s = fabsf(g_stds[d]) + 0.01f;
        float a = sqrtf(2.0f * 3.14159f);
        ginv[d] = 1.f / s;
        gcoef[d] = 1.f / (a * s);
    }
}
__global__ void gauss_csr_k(const float* __restrict__ dist, const int* __restrict__ rowptr,
                            const int* __restrict__ eidx,
                            const float* __restrict__ g_means,
                            const float* __restrict__ ginv, const float* __restrict__ gcoef,
                            const float* __restrict__ scale_param, float* __restrict__ hin) {
    int n = (blockIdx.x * blockDim.x + threadIdx.x) >> 5;
    int lane = threadIdx.x & 31;
    if (n >= NN) return;
    int beg = rowptr[n], end = rowptr[n + 1];
    int degc = min(max(end - beg - 1, 0), MAXDEG - 1);
    float gm[10], gi[10], gc[10], acc[10];
#pragma unroll
    for (int c = 0; c < 10; c++) {
        int d = c * 32 + lane;
        acc[c] = 0.f;
        if (d < DD) { gm[c] = g_means[d]; gi[c] = ginv[d]; gc[c] = gcoef[d]; }
    }
    for (int j = beg; j < end; j++) {
        float de = dist[eidx[j]];
#pragma unroll
        for (int c = 0; c < 10; c++) {
            int d = c * 32 + lane;
            if (d < DD) {
                float z = (de - gm[c]) * gi[c];
                acc[c] += __expf(-0.5f * z * z) * gc[c];
            }
        }
    }
    const float* sp = scale_param + degc * DD;
#pragma unroll
    for (int c = 0; c < 10; c++) {
        int d = c * 32 + lane;
        if (d < DD) hin[(size_t)n * DD + d] = acc[c] * expf(sp[d]);
    }
}

// ---------------- attention fusion -> split "fused" ----------------
__global__ void attn_k(const int* __restrict__ x, const float* __restrict__ atom_emb,
                       const float* __restrict__ att_vec,
                       uint32_t* __restrict__ fh, uint32_t* __restrict__ fl) {
    int warp = (blockIdx.x * blockDim.x + threadIdx.x) >> 5;
    int lane = threadIdx.x & 31;
    if (warp >= NN) return;
    const int* xn = x + warp * 9;
    const float2* emb2 = (const float2*)atom_emb;
    const float2* av2 = (const float2*)att_vec;
    int ids[9];
#pragma unroll
    for (int f = 0; f < 9; f++) ids[f] = (f * 119 + xn[f]) * 150;
    float sc[9];
#pragma unroll
    for (int f = 0; f < 9; f++) {
        float p = 0.f;
        for (int pc = lane; pc < 150; pc += 32) {
            float2 e = emb2[ids[f] + pc];
            float2 a = av2[pc];
            p += e.x * a.x + e.y * a.y;
        }
#pragma unroll
        for (int o = 16; o > 0; o >>= 1) p += __shfl_xor_sync(0xffffffffu, p, o);
        sc[f] = p;
    }
    float m = sc[0];
#pragma unroll
    for (int f = 1; f < 9; f++) m = fmaxf(m, sc[f]);
    float s = 0.f;
#pragma unroll
    for (int f = 0; f < 9; f++) { sc[f] = __expf(sc[f] - m); s += sc[f]; }
    float inv = 1.f / s;
    for (int pc = lane; pc < 150; pc += 32) {
        float2 a = make_float2(0.f, 0.f);
#pragma unroll
        for (int f = 0; f < 9; f++) {
            float2 e = emb2[ids[f] + pc];
            a.x += sc[f] * e.x;
            a.y += sc[f] * e.y;
        }
        uint32_t hi, lo;
        split2(a.x * inv, a.y * inv, hi, lo);
        fh[(size_t)warp * SP300 + pc] = hi;
        fl[(size_t)warp * SP300 + pc] = lo;
    }
}

// ---------------- CSR aggregation with inline BN(+relu) of previous layer ----------------
__global__ void gather_k(const float* __restrict__ h,
                         const int* __restrict__ rowptr, const int* __restrict__ eidx,
                         const int* __restrict__ src, const int* __restrict__ attr,
                         const float* __restrict__ E0, const float* __restrict__ E1,
                         const float* __restrict__ E2,
                         const float* __restrict__ mu, const float* __restrict__ istd,
                         const float* __restrict__ gamma, const float* __restrict__ beta,
                         int apply_bn,
                         uint32_t* __restrict__ aggh, uint32_t* __restrict__ aggl) {
    int n = (blockIdx.x * blockDim.x + threadIdx.x) >> 5;
    int lane = threadIdx.x & 31;
    if (n >= NN) return;
    int beg = rowptr[n], end = rowptr[n + 1];
    const float2* h2 = (const float2*)h;
    const float2* e02 = (const float2*)(E0 + 4 * DD);
    const float2* e12 = (const float2*)E1;
    const float2* e22 = (const float2*)E2;

    float2 scv[5], shv[5];
#pragma unroll
    for (int c = 0; c < 5; c++) {
        int pc = c * 32 + lane;
        if (pc < 150 && apply_bn) {
            float2 g = ((const float2*)gamma)[pc];
            float2 b = ((const float2*)beta)[pc];
            float2 m = ((const float2*)mu)[pc];
            float2 is = ((const float2*)istd)[pc];
            scv[c].x = g.x * is.x; scv[c].y = g.y * is.y;
            shv[c].x = b.x - m.x * scv[c].x; shv[c].y = b.y - m.y * scv[c].y;
        }
    }

    float2 acc[5];
#pragma unroll
    for (int c = 0; c < 5; c++) {
        int pc = c * 32 + lane;
        if (pc < 150) {
            float2 v = h2[(size_t)n * 150 + pc];
            if (apply_bn) {
                v.x = fmaxf(v.x * scv[c].x + shv[c].x, 0.f);
                v.y = fmaxf(v.y * scv[c].y + shv[c].y, 0.f);
            }
            float2 s0 = e02[pc], s1 = e12[pc], s2 = e22[pc];
            acc[c].x = v.x + s0.x + s1.x + s2.x;
            acc[c].y = v.y + s0.y + s1.y + s2.y;
        }
    }
    for (int j = beg; j < end; j++) {
        int e = eidx[j];
        int s = src[e];
        int a0 = attr[e * 3 + 0], a1 = attr[e * 3 + 1], a2 = attr[e * 3 + 2];
        const float2* hs = h2 + (size_t)s * 150;
        const float2* p0 = (const float2*)(E0 + a0 * DD);
        const float2* p1 = (const float2*)(E1 + a1 * DD);
        const float2* p2 = (const float2*)(E2 + a2 * DD);
#pragma unroll
        for (int c = 0; c < 5; c++) {
            int pc = c * 32 + lane;
            if (pc < 150) {
                float2 v = hs[pc];
                if (apply_bn) {
                    v.x = fmaxf(v.x * scv[c].x + shv[c].x, 0.f);
                    v.y = fmaxf(v.y * scv[c].y + shv[c].y, 0.f);
                }
                float2 q0 = p0[pc], q1 = p1[pc], q2 = p2[pc];
                acc[c].x += v.x + q0.x + q1.x + q2.x;
                acc[c].y += v.y + q0.y + q1.y + q2.y;
            }
        }
    }
#pragma unroll
    for (int c = 0; c < 5; c++) {
        int pc = c * 32 + lane;
        if (pc < 150) {
            uint32_t hi, lo;
            split2(acc[c].x, acc[c].y, hi, lo);
            aggh[(size_t)n * SP300 + pc] = hi;
            aggl[(size_t)n * SP300 + pc] = lo;
        }
    }
}

// ---------------- batchnorm stats ----------------
#define BN_RPB 128
__global__ void bn_stats_k(const float* __restrict__ h, float* stats) {
    int row0 = blockIdx.x * BN_RPB;
    int rend = min(row0 + BN_RPB, NN);
    int c0 = threadIdx.x;
    int c1 = threadIdx.x + 256;
    float s0 = 0.f, q0 = 0.f, s1 = 0.f, q1 = 0.f;
    for (int r = row0; r < rend; r++) {
        float v0 = h[(size_t)r * DD + c0];
        s0 += v0; q0 += v0 * v0;
        if (c1 < DD) {
            float v1 = h[(size_t)r * DD + c1];
            s1 += v1; q1 += v1 * v1;
        }
    }
    atomicAdd(&stats[c0], s0);
    atomicAdd(&stats[DD + c0], q0);
    if (c1 < DD) {
        atomicAdd(&stats[c1], s1);
        atomicAdd(&stats[DD + c1], q1);
    }
}
__global__ void bn_fin_k(const float* __restrict__ stats, float* mu, float* istd, float* stats_z) {
    int d = blockIdx.x * blockDim.x + threadIdx.x;
    if (d < DD) {
        float m = stats[d] / (float)NN;
        float v = stats[DD + d] / (float)NN - m * m;
        v = fmaxf(v, 0.f);
        mu[d] = m;
        istd[d] = rsqrtf(v + BN_EPS);
        stats_z[d] = 0.f;
        stats_z[DD + d] = 0.f;
    }
}

// ---------------- pooling with inline BN (last layer, no relu) ----------------
__global__ void gstart_k(const int* __restrict__ batch, int* gstart) {
    int g = blockIdx.x * blockDim.x + threadIdx.x;
    if (g > GG) return;
    int lo = 0, hi = NN;
    while (lo < hi) {
        int mid = (lo + hi) >> 1;
        if (batch[mid] < g) lo = mid + 1; else hi = mid;
    }
    gstart[g] = lo;
}
__global__ void pool_k(const float* __restrict__ h, const int* __restrict__ gstart,
                       const float* __restrict__ mu, const float* __restrict__ istd,
                       const float* __restrict__ gamma, const float* __restrict__ beta,
                       uint32_t* __restrict__ hgh, uint32_t* __restrict__ hgl) {
    int g = blockIdx.x;
    int pc = threadIdx.x;
    if (pc >= 150) return;
    const float2* h2 = (const float2*)h;
    float2 gm = ((const float2*)gamma)[pc];
    float2 bt = ((const float2*)beta)[pc];
    float2 m = ((const float2*)mu)[pc];
    float2 is = ((const float2*)istd)[pc];
    float2 sc, sh;
    sc.x = gm.x * is.x; sc.y = gm.y * is.y;
    sh.x = bt.x - m.x * sc.x; sh.y = bt.y - m.y * sc.y;
    int s = gstart[g], e = gstart[g + 1];
    float2 a = make_float2(0.f, 0.f);
    for (int r = s; r < e; r++) {
        float2 v = h2[(size_t)r * 150 + pc];
        a.x += v.x * sc.x + sh.x;
        a.y += v.y * sc.y + sh.y;
    }
    float inv = 1.f / fmaxf((float)(e - s), 1.f);
    uint32_t hi, lo;
    split2(a.x * inv, a.y * inv, hi, lo);
    hgh[(size_t)g * SP300 + pc] = hi;
    hgl[(size_t)g * SP300 + pc] = lo;
}

// ---------------- host ----------------
static float* symf(const void* sym) { void* p = nullptr; cudaGetSymbolAddress(&p, sym); return (float*)p; }
static int* symi(const void* sym) { void* p = nullptr; cudaGetSymbolAddress(&p, sym); return (int*)p; }
static uint32_t* symu(const void* sym) { void* p = nullptr; cudaGetSymbolAddress(&p, sym); return (uint32_t*)p; }
static inline int cdiv(int a, int b) { return (a + b - 1) / b; }

extern "C" void kernel_launch(void* const* d_in, const int* in_sizes, int n_in,
                              void* d_out, int out_size) {
    const int* x            = (const int*)d_in[0];
    const int* edge_index   = (const int*)d_in[1];
    const int* edge_attr    = (const int*)d_in[2];
    const float* edge_dist  = (const float*)d_in[3];
    const int* batch        = (const int*)d_in[4];
    const float* atom_emb   = (const float*)d_in[5];
    const float* att_vec    = (const float*)d_in[6];
    const float* out_lin_w  = (const float*)d_in[7];
    const float* out_lin_b  = (const float*)d_in[8];
    const float* g_means    = (const float*)d_in[9];
    const float* g_stds     = (const float*)d_in[10];
    const float* scale_par  = (const float*)d_in[11];
    const float* edge_emb   = (const float*)d_in[12];
    const float* mlp_w1     = (const float*)d_in[13];
    const float* mlp_b1     = (const float*)d_in[14];
    const float* mlp_w2     = (const float*)d_in[15];
    const float* mlp_b2     = (const float*)d_in[16];
    const float* bn_gamma   = (const float*)d_in[17];
    const float* bn_beta    = (const float*)d_in[18];
    const float* feat_w     = (const float*)d_in[19];
    const float* feat_b     = (const float*)d_in[20];
    const float* ol_w1      = (const float*)d_in[21];
    const float* ol_b1      = (const float*)d_in[22];
    const float* ol_w2      = (const float*)d_in[23];
    const float* ol_b2      = (const float*)d_in[24];

    const int* e_src = edge_index;
    const int* e_dst = edge_index + EE;

    float* h      = symf(d_h);
    float* hin    = symf(d_hin);
    int*   counts = symi(d_counts);
    int*   cursor = symi(d_cursor);
    int*   rowptr = symi(d_rowptr);
    int*   part   = symi(d_part);
    int*   bsum   = symi(d_bsum);
    int*   eidx   = symi(d_eidx);
    int*   gstart = symi(d_gstart);
    float* stats  = symf(d_stats);
    float* mu     = symf(d_mu);
    float* istd   = symf(d_istd);
    float* ginv   = symf(d_ginv);
    float* gcoef  = symf(d_gcoef);
    uint32_t* aggh = symu(d_aggh), *aggl = symu(d_aggl);
    uint32_t* hidh = symu(d_hidh), *hidl = symu(d_hidl);
    uint32_t* hgh = symu(d_hgh), *hgl = symu(d_hgl);
    uint32_t* hfh = symu(d_hfh), *hfl = symu(d_hfl);
    uint32_t* tbh = symu(d_tbh), *tbl = symu(d_tbl);
    uint32_t* bt0h = symu(d_bt0h), *bt0l = symu(d_bt0l);
    uint32_t* bt1h = symu(d_bt1h), *bt1l = symu(d_bt1l);
    uint32_t* bt2h = symu(d_bt2h), *bt2l = symu(d_bt2l);
    uint32_t* bt3h = symu(d_bt3h), *bt3l = symu(d_bt3l);
    uint32_t* bt4h = symu(d_bt4h), *bt4l = symu(d_bt4l);
    uint32_t* bt5h = symu(d_bt5h), *bt5l = symu(d_bt5l);

    float* out_hfeat = (float*)d_out;
    float* out_final = (float*)d_out + GG * FT;

    const int T = 256;
    cudaFuncSetAttribute(gemm_mma_k, cudaFuncAttributeMaxDynamicSharedMemorySize, GEMM_SMEM);

    // --- weight transposes + bf16 hi/lo split ---
    prep_split_k<<<cdiv(DD * SP300, T), T>>>(out_lin_w, bt0h, bt0l, DD, DD, SP300);
    for (int l = 0; l < LL; l++) {
        prep_split_k<<<cdiv(D2 * SP300, T), T>>>(mlp_w1 + (size_t)l * DD * D2,
                                                 bt1h + (size_t)l * D2 * SP300,
                                                 bt1l + (size_t)l * D2 * SP300, DD, D2, SP300);
        prep_split_k<<<cdiv(DD * SP600, T), T>>>(mlp_w2 + (size_t)l * D2 * DD,
                                                 bt2h + (size_t)l * DD * SP600,
                                                 bt2l + (size_t)l * DD * SP600, D2, DD, SP600);
    }
    prep_split_k<<<cdiv(FT * SP300, T), T>>>(feat_w, bt3h, bt3l, DD, FT, SP300);
    prep_split_k<<<cdiv(FT * SP512, T), T>>>(ol_w1, bt4h, bt4l, FT, FT, SP512);
    prep_split_k<<<cdiv((FT / 2) * SP512, T), T>>>(ol_w2, bt5h, bt5l, FT, FT / 2, SP512);

    // --- CSR build over dst ---
    zero_i<<<cdiv(NN, T), T>>>(counts, NN);
    count_k<<<cdiv(EE, T), T>>>(e_dst, counts);
    {
        int nb = cdiv(NN, 1024);
        scan1_k<<<nb, 1024>>>(counts, part, bsum);
        scan2_k<<<1, 32>>>(bsum, nb);
        scan3_k<<<cdiv(NN, T), T>>>(part, bsum, rowptr);
    }
    zero_i<<<cdiv(NN, T), T>>>(cursor, NN);
    fill_k<<<cdiv(EE, T), T>>>(e_dst, rowptr, cursor, eidx);

    // --- gaussian basis -> hin ---
    gauss_pre_k<<<cdiv(DD, T), T>>>(g_stds, ginv, gcoef);
    gauss_csr_k<<<cdiv(NN * 32, T), T>>>(edge_dist, rowptr, eidx, g_means, ginv, gcoef,
                                         scale_par, hin);

    // --- attention fusion -> split "fused" (in agg arrays) ---
    attn_k<<<cdiv(NN * 32, T), T>>>(x, atom_emb, att_vec, aggh, aggl);

    // --- h = fused @ out_lin_w + b + hin (fp32 out) ---
    {
        dim3 g(cdiv(DD, 128), cdiv(NN, 128));
        gemm_mma_k<<<g, 256, GEMM_SMEM>>>(aggh, aggl, bt0h, bt0l, out_lin_b, hin,
                                          h, nullptr, nullptr, NN, DD, SP300, 0, 0, 1);
    }

    // --- L layers ---
    for (int l = 0; l < LL; l++) {
        const float* E0 = edge_emb + (size_t)(l * 3 + 0) * 5 * DD;
        const float* E1 = edge_emb + (size_t)(l * 3 + 1) * 5 * DD;
        const float* E2 = edge_emb + (size_t)(l * 3 + 2) * 5 * DD;
        // gather with inline BN+relu of previous layer (l>0)
        gather_k<<<cdiv(NN * 32, T), T>>>(h, rowptr, eidx, e_src, edge_attr, E0, E1, E2,
                                          mu, istd, bn_gamma + (l - 1) * DD, bn_beta + (l - 1) * DD,
                                          (l > 0) ? 1 : 0, aggh, aggl);
        {
            dim3 g1(cdiv(D2, 128), cdiv(NN, 128));
            gemm_mma_k<<<g1, 256, GEMM_SMEM>>>(aggh, aggl,
                                               bt1h + (size_t)l * D2 * SP300,
                                               bt1l + (size_t)l * D2 * SP300,
                                               mlp_b1 + l * D2, nullptr,
                                               nullptr, hidh, hidl, NN, D2, SP300, SP600, 1, 0);
            dim3 g2(cdiv(DD, 128), cdiv(NN, 128));
            gemm_mma_k<<<g2, 256, GEMM_SMEM>>>(hidh, hidl,
                                               bt2h + (size_t)l * DD * SP600,
                                               bt2l + (size_t)l * DD * SP600,
                                               mlp_b2 + l * DD, nullptr,
                                               h, nullptr, nullptr, NN, DD, SP600, 0, 0, 0);
        }
        bn_stats_k<<<cdiv(NN, BN_RPB), 256>>>(h, stats);
        bn_fin_k<<<cdiv(DD, T), T>>>(stats, mu, istd, stats);
    }

    // --- pooling with inline BN of last layer ---
    gstart_k<<<cdiv(GG + 1, T), T>>>(batch, gstart);
    pool_k<<<GG, 160>>>(h, gstart, mu, istd, bn_gamma + (LL - 1) * DD, bn_beta + (LL - 1) * DD,
                        hgh, hgl);

    // --- head ---
    {
        dim3 g(cdiv(FT, 128), cdiv(GG, 128));
        gemm_mma_k<<<g, 256, GEMM_SMEM>>>(hgh, hgl, bt3h, bt3l, feat_b, nullptr,
                                          out_hfeat, hfh, hfl, GG, FT, SP300, SP512, 0, 0);
    }
    {
        dim3 g(cdiv(FT, 128), cdiv(GG, 128));
        gemm_mma_k<<<g, 256, GEMM_SMEM>>>(hfh, hfl, bt4h, bt4l, ol_b1, nullptr,
                                          nullptr, tbh, tbl, GG, FT, SP512, SP512, 1, 0);
    }
    {
        dim3 g(cdiv(FT / 2, 128), cdiv(GG, 128));
        gemm_mma_k<<<g, 256, GEMM_SMEM>>>(tbh, tbl, bt5h, bt5l, ol_b2, nullptr,
                                          out_final, nullptr, nullptr, GG, FT / 2, SP512, 0, 0, 0);
    }
}